// round 12
// baseline (speedup 1.0000x reference)
#include <cuda_runtime.h>
#include <math.h>

#define B 64
#define N 512
#define BN (B * N)
#define MLP_H 128
#define N_ACT 512
#define FC_IN 2204            // 512 + 512*3 + 52*3
#define Y_LEN 156
#define NEG_SLOPE 0.2f
#define MAXE 96

// -------- scratch (device globals; zero-initialized at module load) --------
__device__ __align__(16) float g_hes[BN * 8];   // per node: es0,es1,h0,h1 | h2,h3,h4,h5
__device__ __align__(8)  float g_ed[BN * 2];    // per node: ed0,ed1
__device__ __align__(16) float g_h2es[BN * 4];  // per node: es2,h2_0,h2_1,h2_2
__device__ float g_ed2[BN];
__device__ float g_g2[BN * 3];
__device__ float g_hid[B * MLP_H];
__device__ int   g_cnt[BN];                     // zeroed by k_mlp2 tail each call
__device__ short g_src[BN * MAXE];

__device__ __forceinline__ float lrelu(float v) { return v >= 0.f ? v : NEG_SLOPE * v; }
__device__ __forceinline__ float relu(float v)  { return v > 0.f ? v : 0.f; }

// ============ scan (+fused init): adj -> edge lists; per-node h/es/ed; zero g_hid ============
// grid (32, B), 256 threads. Block scans 16 rows of one batch AND initializes 16 nodes.
__global__ void __launch_bounds__(256) k_scan(
        const float* __restrict__ adj, const float* __restrict__ x,
        const float* __restrict__ W1, const float* __restrict__ a_src1,
        const float* __restrict__ a_dst1) {
    const int tid = threadIdx.x;
    const int b = blockIdx.y;
    const int blk = b * 32 + blockIdx.x;           // 0..2047

    // -- fused init: 16 nodes per block (scan does not read these arrays; no sync needed) --
    if (tid < 16) {
        int n = blk * 16 + tid;                    // global node id, covers [0, BN)
        float x0 = x[n * 3 + 0], x1 = x[n * 3 + 1], x2 = x[n * 3 + 2];
        float h[6];
#pragma unroll
        for (int o = 0; o < 6; o++)
            h[o] = x0 * __ldg(&W1[o]) + x1 * __ldg(&W1[6 + o]) + x2 * __ldg(&W1[12 + o]);
        float es0 = h[0] * __ldg(&a_src1[0]) + h[1] * __ldg(&a_src1[1]) + h[2] * __ldg(&a_src1[2]);
        float es1 = h[3] * __ldg(&a_src1[3]) + h[4] * __ldg(&a_src1[4]) + h[5] * __ldg(&a_src1[5]);
        float ed0 = h[0] * __ldg(&a_dst1[0]) + h[1] * __ldg(&a_dst1[1]) + h[2] * __ldg(&a_dst1[2]);
        float ed1 = h[3] * __ldg(&a_dst1[3]) + h[4] * __ldg(&a_dst1[4]) + h[5] * __ldg(&a_dst1[5]);
        *(float4*)&g_hes[(size_t)n * 8]     = make_float4(es0, es1, h[0], h[1]);
        *(float4*)&g_hes[(size_t)n * 8 + 4] = make_float4(h[2], h[3], h[4], h[5]);
        g_ed[n * 2 + 0] = ed0;
        g_ed[n * 2 + 1] = ed1;
    } else if (tid < 20) {
        g_hid[blk * 4 + (tid - 16)] = 0.f;         // 2048*4 = 8192 = B*MLP_H
    }

    // -- adj scan: 16 rows, diagonal skipped (self-loop handled implicitly in agg kernels) --
    const int row0 = blockIdx.x * 16;
    const float4* a4 = (const float4*)(adj + (size_t)b * N * N);
    const int col4 = tid & 127;
    const int rhalf = tid >> 7;
    const int jb = col4 * 4;
#pragma unroll
    for (int it = 0; it < 8; it++) {
        int i = row0 + it * 2 + rhalf;
        float4 av = a4[(size_t)i * 128 + col4];
        if (av.x + av.y + av.z + av.w > 0.f) {     // entries are 0/1
            if (av.x > 0.f && i != jb) {
                int p = atomicAdd(&g_cnt[b * N + jb], 1);
                if (p < MAXE) g_src[(size_t)(b * N + jb) * MAXE + p] = (short)i;
            }
            if (av.y > 0.f && i != jb + 1) {
                int p = atomicAdd(&g_cnt[b * N + jb + 1], 1);
                if (p < MAXE) g_src[(size_t)(b * N + jb + 1) * MAXE + p] = (short)i;
            }
            if (av.z > 0.f && i != jb + 2) {
                int p = atomicAdd(&g_cnt[b * N + jb + 2], 1);
                if (p < MAXE) g_src[(size_t)(b * N + jb + 2) * MAXE + p] = (short)i;
            }
            if (av.w > 0.f && i != jb + 3) {
                int p = atomicAdd(&g_cnt[b * N + jb + 3], 1);
                if (p < MAXE) g_src[(size_t)(b * N + jb + 3) * MAXE + p] = (short)i;
            }
        }
    }
}

// ============ agg1: layer-1 aggregation, 16 lanes per target + h2/es2/ed2 epilogue ============
__global__ void __launch_bounds__(256) k_agg1(
        const float* __restrict__ b1, const float* __restrict__ W2,
        const float* __restrict__ a_src2, const float* __restrict__ a_dst2) {
    int gid = blockIdx.x * 256 + threadIdx.x;      // BN*16 threads
    int t = gid >> 4;
    int sl = gid & 15;
    int b = t >> 9;
    float2 edv = *(const float2*)&g_ed[t * 2];
    int cnt = min(g_cnt[t], MAXE);
    const short* lst = &g_src[(size_t)t * MAXE];

    float s0 = 0.f, s1 = 0.f;
    float A00 = 0.f, A01 = 0.f, A02 = 0.f, A10 = 0.f, A11 = 0.f, A12 = 0.f;
    if (sl == 0) {                                 // implicit self-loop, added exactly once
        float4 p0 = *(const float4*)&g_hes[(size_t)t * 8];
        float4 p1 = *(const float4*)&g_hes[(size_t)t * 8 + 4];
        float e0 = __expf(lrelu(p0.x + edv.x));
        float e1 = __expf(lrelu(p0.y + edv.y));
        s0 = e0; A00 = e0 * p0.z; A01 = e0 * p0.w; A02 = e0 * p1.x;
        s1 = e1; A10 = e1 * p1.y; A11 = e1 * p1.z; A12 = e1 * p1.w;
    }
    for (int e = sl; e < cnt; e += 16) {
        int i = lst[e];
        float4 p0 = *(const float4*)&g_hes[(size_t)(b * N + i) * 8];
        float4 p1 = *(const float4*)&g_hes[(size_t)(b * N + i) * 8 + 4];
        float e0 = __expf(lrelu(p0.x + edv.x));
        float e1 = __expf(lrelu(p0.y + edv.y));
        s0 += e0; A00 += e0 * p0.z; A01 += e0 * p0.w; A02 += e0 * p1.x;
        s1 += e1; A10 += e1 * p1.y; A11 += e1 * p1.z; A12 += e1 * p1.w;
    }
#pragma unroll
    for (int off = 8; off; off >>= 1) {
        s0  += __shfl_xor_sync(0xffffffffu, s0, off);
        s1  += __shfl_xor_sync(0xffffffffu, s1, off);
        A00 += __shfl_xor_sync(0xffffffffu, A00, off);
        A01 += __shfl_xor_sync(0xffffffffu, A01, off);
        A02 += __shfl_xor_sync(0xffffffffu, A02, off);
        A10 += __shfl_xor_sync(0xffffffffu, A10, off);
        A11 += __shfl_xor_sync(0xffffffffu, A11, off);
        A12 += __shfl_xor_sync(0xffffffffu, A12, off);
    }
    if (sl == 0) {
        float i0 = 1.f / s0, i1 = 1.f / s1;
        float g[6];
        g[0] = relu(A00 * i0 + __ldg(&b1[0]));
        g[1] = relu(A01 * i0 + __ldg(&b1[1]));
        g[2] = relu(A02 * i0 + __ldg(&b1[2]));
        g[3] = relu(A10 * i1 + __ldg(&b1[3]));
        g[4] = relu(A11 * i1 + __ldg(&b1[4]));
        g[5] = relu(A12 * i1 + __ldg(&b1[5]));
        // h2 = g1 @ W2; es2/ed2 — computed ONCE per node
        float h0 = 0.f, h1 = 0.f, h2 = 0.f;
#pragma unroll
        for (int f = 0; f < 6; f++) {
            h0 += g[f] * __ldg(&W2[f * 3 + 0]);
            h1 += g[f] * __ldg(&W2[f * 3 + 1]);
            h2 += g[f] * __ldg(&W2[f * 3 + 2]);
        }
        float es2 = h0 * __ldg(&a_src2[0]) + h1 * __ldg(&a_src2[1]) + h2 * __ldg(&a_src2[2]);
        float ed2 = h0 * __ldg(&a_dst2[0]) + h1 * __ldg(&a_dst2[1]) + h2 * __ldg(&a_dst2[2]);
        *(float4*)&g_h2es[(size_t)t * 4] = make_float4(es2, h0, h1, h2);
        g_ed2[t] = ed2;
    }
}

// ============ agg2: layer-2 aggregation, 16 lanes per target, 16B/edge ============
__global__ void __launch_bounds__(256) k_agg2(const float* __restrict__ b2) {
    int gid = blockIdx.x * 256 + threadIdx.x;      // BN*16 threads
    int t = gid >> 4;
    int sl = gid & 15;
    int b = t >> 9;
    float edj = g_ed2[t];
    int cnt = min(g_cnt[t], MAXE);
    const short* lst = &g_src[(size_t)t * MAXE];

    float s = 0.f, a0 = 0.f, a1 = 0.f, a2 = 0.f;
    if (sl == 0) {                                 // implicit self-loop
        float4 q = *(const float4*)&g_h2es[(size_t)t * 4];
        float ev = __expf(lrelu(q.x + edj));
        s = ev; a0 = ev * q.y; a1 = ev * q.z; a2 = ev * q.w;
    }
    for (int e = sl; e < cnt; e += 16) {
        int i = lst[e];
        float4 q = *(const float4*)&g_h2es[(size_t)(b * N + i) * 4];
        float ev = __expf(lrelu(q.x + edj));
        s += ev; a0 += ev * q.y; a1 += ev * q.z; a2 += ev * q.w;
    }
#pragma unroll
    for (int off = 8; off; off >>= 1) {
        s  += __shfl_xor_sync(0xffffffffu, s, off);
        a0 += __shfl_xor_sync(0xffffffffu, a0, off);
        a1 += __shfl_xor_sync(0xffffffffu, a1, off);
        a2 += __shfl_xor_sync(0xffffffffu, a2, off);
    }
    if (sl == 0) {
        float inv = 1.f / s;
        g_g2[(size_t)t * 3 + 0] = a0 * inv + __ldg(&b2[0]);
        g_g2[(size_t)t * 3 + 1] = a1 * inv + __ldg(&b2[1]);
        g_g2[(size_t)t * 3 + 2] = a2 * inv + __ldg(&b2[2]);
    }
}

// ============ mlp1: tiled layer-1 GEMM; grid (4 hid x 69 k x 4 batch) = 1104 blocks ============
#define KT1 32
#define KTILES1 69            // 69*32 = 2208 >= 2204 (zero-padded)
#define HT1 32
#define BT1 16
__global__ void __launch_bounds__(256) k_mlp1(
        const float* __restrict__ idx, const float* __restrict__ y,
        const float* __restrict__ Wf1) {
    __shared__ float Wsh[KT1 * HT1];               // [k][h], 4 KB
    __shared__ float fsh[BT1 * (KT1 + 1)];         // [b][k] pad, 2.1 KB

    const int tid = threadIdx.x;
    const int hid0 = blockIdx.x * HT1;
    const int k0 = blockIdx.y * KT1;
    const int b0 = blockIdx.z * BT1;

    // Wsh: 1024 elems, 4/thread; lanes vary h -> coalesced; zero-pad past FC_IN
#pragma unroll
    for (int i = 0; i < (KT1 * HT1) / 256; i++) {
        int e = tid + i * 256;
        int k = e >> 5, h = e & 31;
        int kk = k0 + k;
        Wsh[e] = (kk < FC_IN) ? Wf1[kk * MLP_H + hid0 + h] : 0.f;
    }
    // fsh: 512 elems, 2/thread; lanes vary k -> coalesced gathers
#pragma unroll
    for (int i = 0; i < (BT1 * KT1) / 256; i++) {
        int e = tid + i * 256;
        int bb = e >> 5, k = e & 31;
        int kk = k0 + k;
        int b = b0 + bb;
        float v = 0.f;
        if (kk < 512)            v = idx[b * 512 + kk];
        else if (kk < 2048)      v = g_g2[b * 1536 + (kk - 512)];
        else if (kk < FC_IN)     v = y[b * Y_LEN + (kk - 2048)];
        fsh[bb * (KT1 + 1) + k] = v;
    }
    __syncthreads();

    // thread: bb = tid&15 (stride-33 fsh -> conflict-free), h-pair = (tid>>4)*2
    const int bb = tid & 15;
    const int h2 = (tid >> 4) * 2;
    float a0 = 0.f, a1 = 0.f;
#pragma unroll
    for (int k = 0; k < KT1; k++) {
        float f = fsh[bb * (KT1 + 1) + k];
        float2 w = *(const float2*)&Wsh[k * HT1 + h2];
        a0 += f * w.x;
        a1 += f * w.y;
    }
    atomicAdd(&g_hid[(b0 + bb) * MLP_H + hid0 + h2], a0);
    atomicAdd(&g_hid[(b0 + bb) * MLP_H + hid0 + h2 + 1], a1);
}

// ============ mlp2: out = relu(hid+bf1) @ Wf2 + bf2; tail re-zeroes g_cnt ============
__global__ void __launch_bounds__(256) k_mlp2(
        const float* __restrict__ bf1, const float* __restrict__ Wf2,
        const float* __restrict__ bf2, float* __restrict__ out) {
    __shared__ float sh[MLP_H];
    const int b = blockIdx.x >> 1;
    const int o = (blockIdx.x & 1) * 256 + threadIdx.x;
    if (threadIdx.x < MLP_H)
        sh[threadIdx.x] = relu(g_hid[b * MLP_H + threadIdx.x] + __ldg(&bf1[threadIdx.x]));
    __syncthreads();
    float acc = __ldg(&bf2[o]);
#pragma unroll 8
    for (int t = 0; t < MLP_H; t++)
        acc += sh[t] * Wf2[t * N_ACT + o];
    out[b * N_ACT + o] = acc;
    // re-zero edge counters for the next invocation (128 blocks * 256 threads = BN exactly)
    g_cnt[blockIdx.x * 256 + threadIdx.x] = 0;
}

extern "C" void kernel_launch(void* const* d_in, const int* in_sizes, int n_in,
                              void* d_out, int out_size) {
    const float* idx    = (const float*)d_in[0];
    const float* x      = (const float*)d_in[1];
    const float* y      = (const float*)d_in[2];
    const float* adj    = (const float*)d_in[3];
    const float* W1     = (const float*)d_in[4];
    const float* a_src1 = (const float*)d_in[5];
    const float* a_dst1 = (const float*)d_in[6];
    const float* b1     = (const float*)d_in[7];
    const float* W2     = (const float*)d_in[8];
    const float* a_src2 = (const float*)d_in[9];
    const float* a_dst2 = (const float*)d_in[10];
    const float* b2     = (const float*)d_in[11];
    const float* Wf1    = (const float*)d_in[12];
    const float* bf1    = (const float*)d_in[13];
    const float* Wf2    = (const float*)d_in[14];
    const float* bf2    = (const float*)d_in[15];
    float* out = (float*)d_out;

    k_scan<<<dim3(32, B), 256>>>(adj, x, W1, a_src1, a_dst1);
    k_agg1<<<BN * 16 / 256, 256>>>(b1, W2, a_src2, a_dst2);
    k_agg2<<<BN * 16 / 256, 256>>>(b2);
    k_mlp1<<<dim3(MLP_H / HT1, KTILES1, B / BT1), 256>>>(idx, y, Wf1);
    k_mlp2<<<B * 2, 256>>>(bf1, Wf2, bf2, out);
}

// round 15
// speedup vs baseline: 1.1206x; 1.1206x over previous
#include <cuda_runtime.h>
#include <math.h>

#define B 64
#define N 512
#define BN (B * N)
#define MLP_H 128
#define N_ACT 512
#define FC_IN 2204            // 512 + 512*3 + 52*3
#define Y_LEN 156
#define NEG_SLOPE 0.2f
#define MAXE 96

// -------- scratch (device globals; zero-initialized at module load) --------
__device__ __align__(16) float g_hes[BN * 8];   // per node: es0,es1,h0,h1 | h2,h3,h4,h5
__device__ __align__(8)  float g_ed[BN * 2];    // per node: ed0,ed1
__device__ __align__(16) float g_h2es[BN * 4];  // per node: es2,h2_0,h2_1,h2_2
__device__ float g_ed2[BN];
__device__ float g_g2[BN * 3];
__device__ float g_hid[B * MLP_H];
__device__ int   g_cnt[BN];                     // zeroed by k_mlp2 tail each call
__device__ short g_src[BN * MAXE];

__device__ __forceinline__ float lrelu(float v) { return v >= 0.f ? v : NEG_SLOPE * v; }
__device__ __forceinline__ float relu(float v)  { return v > 0.f ? v : 0.f; }

// ============ scan (+fused init): adj -> edge lists; per-node h/es/ed; zero g_hid ============
// grid (32, B), 256 threads. Block scans 16 rows of one batch AND initializes 16 nodes.
__global__ void __launch_bounds__(256) k_scan(
        const float* __restrict__ adj, const float* __restrict__ x,
        const float* __restrict__ W1, const float* __restrict__ a_src1,
        const float* __restrict__ a_dst1) {
    const int tid = threadIdx.x;
    const int b = blockIdx.y;
    const int blk = b * 32 + blockIdx.x;           // 0..2047

    // -- fused init: 16 nodes per block (scan does not read these arrays; no sync needed) --
    if (tid < 16) {
        int n = blk * 16 + tid;                    // global node id, covers [0, BN)
        float x0 = x[n * 3 + 0], x1 = x[n * 3 + 1], x2 = x[n * 3 + 2];
        float h[6];
#pragma unroll
        for (int o = 0; o < 6; o++)
            h[o] = x0 * __ldg(&W1[o]) + x1 * __ldg(&W1[6 + o]) + x2 * __ldg(&W1[12 + o]);
        float es0 = h[0] * __ldg(&a_src1[0]) + h[1] * __ldg(&a_src1[1]) + h[2] * __ldg(&a_src1[2]);
        float es1 = h[3] * __ldg(&a_src1[3]) + h[4] * __ldg(&a_src1[4]) + h[5] * __ldg(&a_src1[5]);
        float ed0 = h[0] * __ldg(&a_dst1[0]) + h[1] * __ldg(&a_dst1[1]) + h[2] * __ldg(&a_dst1[2]);
        float ed1 = h[3] * __ldg(&a_dst1[3]) + h[4] * __ldg(&a_dst1[4]) + h[5] * __ldg(&a_dst1[5]);
        *(float4*)&g_hes[(size_t)n * 8]     = make_float4(es0, es1, h[0], h[1]);
        *(float4*)&g_hes[(size_t)n * 8 + 4] = make_float4(h[2], h[3], h[4], h[5]);
        g_ed[n * 2 + 0] = ed0;
        g_ed[n * 2 + 1] = ed1;
    } else if (tid < 20) {
        g_hid[blk * 4 + (tid - 16)] = 0.f;         // 2048*4 = 8192 = B*MLP_H
    }

    // -- adj scan: 16 rows, diagonal skipped (self-loop handled implicitly in agg kernels) --
    const int row0 = blockIdx.x * 16;
    const float4* a4 = (const float4*)(adj + (size_t)b * N * N);
    const int col4 = tid & 127;
    const int rhalf = tid >> 7;
    const int jb = col4 * 4;
#pragma unroll
    for (int it = 0; it < 8; it++) {
        int i = row0 + it * 2 + rhalf;
        float4 av = a4[(size_t)i * 128 + col4];
        if (av.x + av.y + av.z + av.w > 0.f) {     // entries are 0/1
            if (av.x > 0.f && i != jb) {
                int p = atomicAdd(&g_cnt[b * N + jb], 1);
                if (p < MAXE) g_src[(size_t)(b * N + jb) * MAXE + p] = (short)i;
            }
            if (av.y > 0.f && i != jb + 1) {
                int p = atomicAdd(&g_cnt[b * N + jb + 1], 1);
                if (p < MAXE) g_src[(size_t)(b * N + jb + 1) * MAXE + p] = (short)i;
            }
            if (av.z > 0.f && i != jb + 2) {
                int p = atomicAdd(&g_cnt[b * N + jb + 2], 1);
                if (p < MAXE) g_src[(size_t)(b * N + jb + 2) * MAXE + p] = (short)i;
            }
            if (av.w > 0.f && i != jb + 3) {
                int p = atomicAdd(&g_cnt[b * N + jb + 3], 1);
                if (p < MAXE) g_src[(size_t)(b * N + jb + 3) * MAXE + p] = (short)i;
            }
        }
    }
}

// ============ agg1: layer-1 aggregation, 8 lanes per target + h2/es2/ed2 epilogue ============
__global__ void __launch_bounds__(256) k_agg1(
        const float* __restrict__ b1, const float* __restrict__ W2,
        const float* __restrict__ a_src2, const float* __restrict__ a_dst2) {
    int gid = blockIdx.x * 256 + threadIdx.x;      // BN*8 threads
    int t = gid >> 3;
    int sl = gid & 7;
    int b = t >> 9;
    float2 edv = *(const float2*)&g_ed[t * 2];
    int cnt = min(g_cnt[t], MAXE);
    const short* lst = &g_src[(size_t)t * MAXE];

    float s0 = 0.f, s1 = 0.f;
    float A00 = 0.f, A01 = 0.f, A02 = 0.f, A10 = 0.f, A11 = 0.f, A12 = 0.f;
    if (sl == 0) {                                 // implicit self-loop, added exactly once
        float4 p0 = *(const float4*)&g_hes[(size_t)t * 8];
        float4 p1 = *(const float4*)&g_hes[(size_t)t * 8 + 4];
        float e0 = __expf(lrelu(p0.x + edv.x));
        float e1 = __expf(lrelu(p0.y + edv.y));
        s0 = e0; A00 = e0 * p0.z; A01 = e0 * p0.w; A02 = e0 * p1.x;
        s1 = e1; A10 = e1 * p1.y; A11 = e1 * p1.z; A12 = e1 * p1.w;
    }
    for (int e = sl; e < cnt; e += 8) {
        int i = lst[e];
        float4 p0 = *(const float4*)&g_hes[(size_t)(b * N + i) * 8];
        float4 p1 = *(const float4*)&g_hes[(size_t)(b * N + i) * 8 + 4];
        float e0 = __expf(lrelu(p0.x + edv.x));
        float e1 = __expf(lrelu(p0.y + edv.y));
        s0 += e0; A00 += e0 * p0.z; A01 += e0 * p0.w; A02 += e0 * p1.x;
        s1 += e1; A10 += e1 * p1.y; A11 += e1 * p1.z; A12 += e1 * p1.w;
    }
#pragma unroll
    for (int off = 4; off; off >>= 1) {
        s0  += __shfl_xor_sync(0xffffffffu, s0, off);
        s1  += __shfl_xor_sync(0xffffffffu, s1, off);
        A00 += __shfl_xor_sync(0xffffffffu, A00, off);
        A01 += __shfl_xor_sync(0xffffffffu, A01, off);
        A02 += __shfl_xor_sync(0xffffffffu, A02, off);
        A10 += __shfl_xor_sync(0xffffffffu, A10, off);
        A11 += __shfl_xor_sync(0xffffffffu, A11, off);
        A12 += __shfl_xor_sync(0xffffffffu, A12, off);
    }
    if (sl == 0) {
        float i0 = 1.f / s0, i1 = 1.f / s1;
        float g[6];
        g[0] = relu(A00 * i0 + __ldg(&b1[0]));
        g[1] = relu(A01 * i0 + __ldg(&b1[1]));
        g[2] = relu(A02 * i0 + __ldg(&b1[2]));
        g[3] = relu(A10 * i1 + __ldg(&b1[3]));
        g[4] = relu(A11 * i1 + __ldg(&b1[4]));
        g[5] = relu(A12 * i1 + __ldg(&b1[5]));
        // h2 = g1 @ W2; es2/ed2 — computed ONCE per node
        float h0 = 0.f, h1 = 0.f, h2 = 0.f;
#pragma unroll
        for (int f = 0; f < 6; f++) {
            h0 += g[f] * __ldg(&W2[f * 3 + 0]);
            h1 += g[f] * __ldg(&W2[f * 3 + 1]);
            h2 += g[f] * __ldg(&W2[f * 3 + 2]);
        }
        float es2 = h0 * __ldg(&a_src2[0]) + h1 * __ldg(&a_src2[1]) + h2 * __ldg(&a_src2[2]);
        float ed2 = h0 * __ldg(&a_dst2[0]) + h1 * __ldg(&a_dst2[1]) + h2 * __ldg(&a_dst2[2]);
        *(float4*)&g_h2es[(size_t)t * 4] = make_float4(es2, h0, h1, h2);
        g_ed2[t] = ed2;
    }
}

// ============ agg2: layer-2 aggregation, 8 lanes per target, 16B/edge ============
__global__ void __launch_bounds__(256) k_agg2(const float* __restrict__ b2) {
    int gid = blockIdx.x * 256 + threadIdx.x;      // BN*8 threads
    int t = gid >> 3;
    int sl = gid & 7;
    int b = t >> 9;
    float edj = g_ed2[t];
    int cnt = min(g_cnt[t], MAXE);
    const short* lst = &g_src[(size_t)t * MAXE];

    float s = 0.f, a0 = 0.f, a1 = 0.f, a2 = 0.f;
    if (sl == 0) {                                 // implicit self-loop
        float4 q = *(const float4*)&g_h2es[(size_t)t * 4];
        float ev = __expf(lrelu(q.x + edj));
        s = ev; a0 = ev * q.y; a1 = ev * q.z; a2 = ev * q.w;
    }
    for (int e = sl; e < cnt; e += 8) {
        int i = lst[e];
        float4 q = *(const float4*)&g_h2es[(size_t)(b * N + i) * 4];
        float ev = __expf(lrelu(q.x + edj));
        s += ev; a0 += ev * q.y; a1 += ev * q.z; a2 += ev * q.w;
    }
#pragma unroll
    for (int off = 4; off; off >>= 1) {
        s  += __shfl_xor_sync(0xffffffffu, s, off);
        a0 += __shfl_xor_sync(0xffffffffu, a0, off);
        a1 += __shfl_xor_sync(0xffffffffu, a1, off);
        a2 += __shfl_xor_sync(0xffffffffu, a2, off);
    }
    if (sl == 0) {
        float inv = 1.f / s;
        g_g2[(size_t)t * 3 + 0] = a0 * inv + __ldg(&b2[0]);
        g_g2[(size_t)t * 3 + 1] = a1 * inv + __ldg(&b2[1]);
        g_g2[(size_t)t * 3 + 2] = a2 * inv + __ldg(&b2[2]);
    }
}

// ============ mlp1: tiled layer-1 GEMM; grid (4 hid x 35 k x 4 batch) = 560 blocks ============
#define KT1 64
#define KTILES1 35            // 35*64 = 2240 >= 2204 (zero-padded)
#define HT1 32
#define BT1 16
__global__ void __launch_bounds__(256) k_mlp1(
        const float* __restrict__ idx, const float* __restrict__ y,
        const float* __restrict__ Wf1) {
    __shared__ float Wsh[KT1 * HT1];               // [k][h], 8 KB
    __shared__ float fsh[BT1 * (KT1 + 1)];         // [b][k] pad, 4.2 KB

    const int tid = threadIdx.x;
    const int hid0 = blockIdx.x * HT1;
    const int k0 = blockIdx.y * KT1;
    const int b0 = blockIdx.z * BT1;

    // Wsh: lanes vary h -> coalesced; zero-pad past FC_IN
#pragma unroll
    for (int i = 0; i < (KT1 * HT1) / 256; i++) {
        int e = tid + i * 256;
        int k = e >> 5, h = e & 31;
        int kk = k0 + k;
        Wsh[e] = (kk < FC_IN) ? Wf1[kk * MLP_H + hid0 + h] : 0.f;
    }
    // fsh: 1024 elems, 4/thread; lanes vary k -> coalesced gathers
#pragma unroll
    for (int i = 0; i < (BT1 * KT1) / 256; i++) {
        int e = tid + i * 256;
        int bb = e >> 6, k = e & 63;
        int kk = k0 + k;
        int b = b0 + bb;
        float v = 0.f;
        if (kk < 512)            v = idx[b * 512 + kk];
        else if (kk < 2048)      v = g_g2[b * 1536 + (kk - 512)];
        else if (kk < FC_IN)     v = y[b * Y_LEN + (kk - 2048)];
        fsh[bb * (KT1 + 1) + k] = v;
    }
    __syncthreads();

    // thread: bb = tid&15 (stride-65 fsh -> conflict-free), h-pair = (tid>>4)*2
    const int bb = tid & 15;
    const int h2 = (tid >> 4) * 2;
    float a0 = 0.f, a1 = 0.f;
#pragma unroll 8
    for (int k = 0; k < KT1; k++) {
        float f = fsh[bb * (KT1 + 1) + k];
        float2 w = *(const float2*)&Wsh[k * HT1 + h2];
        a0 += f * w.x;
        a1 += f * w.y;
    }
    atomicAdd(&g_hid[(b0 + bb) * MLP_H + hid0 + h2], a0);
    atomicAdd(&g_hid[(b0 + bb) * MLP_H + hid0 + h2 + 1], a1);
}

// ============ mlp2: out = relu(hid+bf1) @ Wf2 + bf2; tail re-zeroes g_cnt ============
__global__ void __launch_bounds__(256) k_mlp2(
        const float* __restrict__ bf1, const float* __restrict__ Wf2,
        const float* __restrict__ bf2, float* __restrict__ out) {
    __shared__ float sh[MLP_H];
    const int b = blockIdx.x >> 1;
    const int o = (blockIdx.x & 1) * 256 + threadIdx.x;
    if (threadIdx.x < MLP_H)
        sh[threadIdx.x] = relu(g_hid[b * MLP_H + threadIdx.x] + __ldg(&bf1[threadIdx.x]));
    __syncthreads();
    float acc = __ldg(&bf2[o]);
#pragma unroll 8
    for (int t = 0; t < MLP_H; t++)
        acc += sh[t] * Wf2[t * N_ACT + o];
    out[b * N_ACT + o] = acc;
    // re-zero edge counters for the next invocation (128 blocks * 256 threads = BN exactly)
    g_cnt[blockIdx.x * 256 + threadIdx.x] = 0;
}

extern "C" void kernel_launch(void* const* d_in, const int* in_sizes, int n_in,
                              void* d_out, int out_size) {
    const float* idx    = (const float*)d_in[0];
    const float* x      = (const float*)d_in[1];
    const float* y      = (const float*)d_in[2];
    const float* adj    = (const float*)d_in[3];
    const float* W1     = (const float*)d_in[4];
    const float* a_src1 = (const float*)d_in[5];
    const float* a_dst1 = (const float*)d_in[6];
    const float* b1     = (const float*)d_in[7];
    const float* W2     = (const float*)d_in[8];
    const float* a_src2 = (const float*)d_in[9];
    const float* a_dst2 = (const float*)d_in[10];
    const float* b2     = (const float*)d_in[11];
    const float* Wf1    = (const float*)d_in[12];
    const float* bf1    = (const float*)d_in[13];
    const float* Wf2    = (const float*)d_in[14];
    const float* bf2    = (const float*)d_in[15];
    float* out = (float*)d_out;

    k_scan<<<dim3(32, B), 256>>>(adj, x, W1, a_src1, a_dst1);
    k_agg1<<<BN * 8 / 256, 256>>>(b1, W2, a_src2, a_dst2);
    k_agg2<<<BN * 8 / 256, 256>>>(b2);
    k_mlp1<<<dim3(MLP_H / HT1, KTILES1, B / BT1), 256>>>(idx, y, Wf1);
    k_mlp2<<<B * 2, 256>>>(bf1, Wf2, bf2, out);
}